// round 4
// baseline (speedup 1.0000x reference)
#include <cuda_runtime.h>

// PrototypeField: B=262144, D=256, C=128.
// out[0] = 0.1*(1 - mean cos_sim), out[1..32768] = new_v (C,D).
//
// Identity: sum_i <dirs_n_i, new_v[label_i]> = sum_c <sums_c, new_v_c>,
// so dirs is read exactly once (268 MB -> HBM-bound floor ~34us).
//
// accum_kernel (148 CTAs x 1024): phase A builds per-(warp,class) row lists
// in smem via ballot counting sort; phase B walks each class sublist with
// 2-row batches + next-batch prefetch (8 LDG.128 in flight/warp), register
// accumulation (8 floats/lane/class), one float4-atomic flush per class.
// finalize_kernel: EMA + renormalize + loss, then re-zeros g_sums/g_counts
// so each graph replay sees identical state (no zero kernel needed).

#define DD 256
#define CC 128
#define GRID1 148
#define T1 1024
#define FULLM 0xFFFFFFFFu
#define MAXROWS 1824

__device__ float g_sums[CC * DD];   // zero-initialized at module load
__device__ float g_counts[CC];

#define DOT8(p, q) ((p).x*(p).x + (p).y*(p).y + (p).z*(p).z + (p).w*(p).w \
                  + (q).x*(q).x + (q).y*(q).y + (q).z*(q).z + (q).w*(q).w)
#define AXPY4(acc, v, s) do { (acc).x += (v).x*(s); (acc).y += (v).y*(s); \
                              (acc).z += (v).z*(s); (acc).w += (v).w*(s); } while (0)

__global__ __launch_bounds__(T1, 1) void accum_kernel(
    const float* __restrict__ dirs,
    const int* __restrict__ labels,
    int B)
{
    __shared__ int labs[MAXROWS];
    __shared__ unsigned short list[MAXROWS];
    __shared__ int ccount[CC];
    __shared__ int cbase[CC + 1];

    const int tid  = threadIdx.x;
    const int wid  = tid >> 5;          // warp owns classes [4*wid, 4*wid+4)
    const int lane = tid & 31;
    const int base_c = wid << 2;

    const int rows_per = (B + GRID1 - 1) / GRID1;   // 1772
    const int row0  = blockIdx.x * rows_per;
    const int nrows = min(rows_per, B - row0);
    if (nrows <= 0) return;

    for (int i = tid; i < nrows; i += T1) labs[i] = labels[row0 + i];
    __syncthreads();

    // ---- Phase A1: per-class counts (warp-uniform via ballot popc) ----
    int c0 = 0, c1 = 0, c2 = 0, c3 = 0;
    for (int b = 0; b < nrows; b += 32) {
        int r = b + lane;
        int lab = (r < nrows) ? labs[r] : -1;
        c0 += __popc(__ballot_sync(FULLM, lab == base_c));
        c1 += __popc(__ballot_sync(FULLM, lab == base_c + 1));
        c2 += __popc(__ballot_sync(FULLM, lab == base_c + 2));
        c3 += __popc(__ballot_sync(FULLM, lab == base_c + 3));
    }
    if (lane == 0) {
        ccount[base_c]     = c0;
        ccount[base_c + 1] = c1;
        ccount[base_c + 2] = c2;
        ccount[base_c + 3] = c3;
    }
    __syncthreads();

    // ---- Phase A2: exclusive prefix over 128 class counts (warp 0) ----
    if (wid == 0) {
        int k0 = ccount[lane * 4], k1 = ccount[lane * 4 + 1];
        int k2 = ccount[lane * 4 + 2], k3 = ccount[lane * 4 + 3];
        int s = k0 + k1 + k2 + k3;
        int x = s;
        #pragma unroll
        for (int o = 1; o < 32; o <<= 1) {
            int y = __shfl_up_sync(FULLM, x, o);
            if (lane >= o) x += y;
        }
        int excl = x - s;
        cbase[lane * 4]     = excl;
        cbase[lane * 4 + 1] = excl + k0;
        cbase[lane * 4 + 2] = excl + k0 + k1;
        cbase[lane * 4 + 3] = excl + k0 + k1 + k2;
        if (lane == 31) cbase[CC] = excl + s;
    }
    __syncthreads();

    // ---- Phase A3: fill class-sorted row lists ----
    {
        int o0 = cbase[base_c],     o1 = cbase[base_c + 1];
        int o2 = cbase[base_c + 2], o3 = cbase[base_c + 3];
        unsigned below = (1u << lane) - 1u;
        for (int b = 0; b < nrows; b += 32) {
            int r = b + lane;
            int lab = (r < nrows) ? labs[r] : -1;
            unsigned m0 = __ballot_sync(FULLM, lab == base_c);
            unsigned m1 = __ballot_sync(FULLM, lab == base_c + 1);
            unsigned m2 = __ballot_sync(FULLM, lab == base_c + 2);
            unsigned m3 = __ballot_sync(FULLM, lab == base_c + 3);
            if (lab == base_c)          list[o0 + __popc(m0 & below)] = (unsigned short)r;
            else if (lab == base_c + 1) list[o1 + __popc(m1 & below)] = (unsigned short)r;
            else if (lab == base_c + 2) list[o2 + __popc(m2 & below)] = (unsigned short)r;
            else if (lab == base_c + 3) list[o3 + __popc(m3 & below)] = (unsigned short)r;
            o0 += __popc(m0); o1 += __popc(m1);
            o2 += __popc(m2); o3 += __popc(m3);
        }
    }
    __syncthreads();

    // ---- Phase B: per-class accumulation, 2-row batches + prefetch ----
    const float4* dbase = (const float4*)dirs + (long long)row0 * (DD / 4);
    const float4 z = make_float4(0.f, 0.f, 0.f, 0.f);

    #pragma unroll 1
    for (int k = 0; k < 4; k++) {
        int c = base_c + k;
        int s = cbase[c], e = cbase[c + 1];
        if (s >= e) continue;

        float4 AL = z, AH = z;

        int i = s;
        int r1 = (i + 1 < e) ? (int)list[i + 1] : -1;
        const float4* p0 = dbase + (long long)(int)list[i] * 64;
        float4 a0 = __ldg(p0 + lane), a1 = __ldg(p0 + lane + 32);
        float4 b0 = z, b1 = z;
        if (r1 >= 0) {
            const float4* p1 = dbase + (long long)r1 * 64;
            b0 = __ldg(p1 + lane); b1 = __ldg(p1 + lane + 32);
        }

        for (;;) {
            int ni = i + 2;
            int nr1 = -1;
            float4 na0 = z, na1 = z, nb0 = z, nb1 = z;
            if (ni < e) {
                const float4* q0 = dbase + (long long)(int)list[ni] * 64;
                na0 = __ldg(q0 + lane); na1 = __ldg(q0 + lane + 32);
                if (ni + 1 < e) {
                    nr1 = (int)list[ni + 1];
                    const float4* q1 = dbase + (long long)nr1 * 64;
                    nb0 = __ldg(q1 + lane); nb1 = __ldg(q1 + lane + 32);
                }
            }

            // two interleaved warp allreduces
            float s0 = DOT8(a0, a1);
            float s1 = DOT8(b0, b1);
            #pragma unroll
            for (int o = 16; o > 0; o >>= 1) {
                s0 += __shfl_xor_sync(FULLM, s0, o);
                s1 += __shfl_xor_sync(FULLM, s1, o);
            }
            float i0 = 1.0f / fmaxf(sqrtf(s0), 1e-12f);
            AXPY4(AL, a0, i0); AXPY4(AH, a1, i0);
            if (r1 >= 0) {
                float i1 = 1.0f / fmaxf(sqrtf(s1), 1e-12f);
                AXPY4(AL, b0, i1); AXPY4(AH, b1, i1);
            }

            if (ni >= e) break;
            i = ni; r1 = nr1;
            a0 = na0; a1 = na1; b0 = nb0; b1 = nb1;
        }

        // single vector-atomic flush per (warp, class)
        float* sp = g_sums + c * DD + (lane << 2);
        atomicAdd((float4*)sp, AL);
        atomicAdd((float4*)(sp + 128), AH);
        if (lane == 0) atomicAdd(&g_counts[c], (float)(e - s));
    }
}

__global__ __launch_bounds__(1024, 1) void finalize_kernel(
    const float* __restrict__ v_class,
    const int* __restrict__ step_ptr,
    float* __restrict__ out,
    float Bf)
{
    __shared__ float wdots[32];
    const int tid  = threadIdx.x;
    const int wid  = tid >> 5;
    const int lane = tid & 31;

    float stepf = (float)(*step_ptr);
    float alpha = fminf(0.02f, stepf / (stepf + 50.0f));
    float oma = 1.0f - alpha;

    float warpDot = 0.0f;

    #pragma unroll
    for (int k = 0; k < 4; k++) {
        int c = (wid << 2) + k;
        const float4* sp = (const float4*)(g_sums + c * DD);
        float4 s0 = sp[lane];
        float4 s1 = sp[lane + 32];
        float cnt = g_counts[c];

        float invc = 1.0f / fmaxf(cnt, 1.0f);
        float4 b0, b1;
        b0.x = s0.x * invc; b0.y = s0.y * invc; b0.z = s0.z * invc; b0.w = s0.w * invc;
        b1.x = s1.x * invc; b1.y = s1.y * invc; b1.z = s1.z * invc; b1.w = s1.w * invc;

        float nb = DOT8(b0, b1);
        #pragma unroll
        for (int o = 16; o > 0; o >>= 1) nb += __shfl_xor_sync(FULLM, nb, o);
        float invb = 1.0f / fmaxf(sqrtf(nb), 1e-12f);

        const float4* vp = (const float4*)(v_class + c * DD);
        float4 vc0 = vp[lane];
        float4 vc1 = vp[lane + 32];

        float4 u0, u1;
        u0.x = oma * vc0.x + alpha * b0.x * invb;
        u0.y = oma * vc0.y + alpha * b0.y * invb;
        u0.z = oma * vc0.z + alpha * b0.z * invb;
        u0.w = oma * vc0.w + alpha * b0.w * invb;
        u1.x = oma * vc1.x + alpha * b1.x * invb;
        u1.y = oma * vc1.y + alpha * b1.y * invb;
        u1.z = oma * vc1.z + alpha * b1.z * invb;
        u1.w = oma * vc1.w + alpha * b1.w * invb;

        float nu = DOT8(u0, u1);
        #pragma unroll
        for (int o = 16; o > 0; o >>= 1) nu += __shfl_xor_sync(FULLM, nu, o);
        float invu = 1.0f / fmaxf(sqrtf(nu), 1e-12f);

        bool use = (cnt > 0.0f);
        float w0x = use ? u0.x * invu : vc0.x;
        float w0y = use ? u0.y * invu : vc0.y;
        float w0z = use ? u0.z * invu : vc0.z;
        float w0w = use ? u0.w * invu : vc0.w;
        float w1x = use ? u1.x * invu : vc1.x;
        float w1y = use ? u1.y * invu : vc1.y;
        float w1z = use ? u1.z * invu : vc1.z;
        float w1w = use ? u1.w * invu : vc1.w;

        float* op = out + 1 + c * DD + (lane << 2);
        op[0] = w0x; op[1] = w0y; op[2] = w0z; op[3] = w0w;
        op[128] = w1x; op[129] = w1y; op[130] = w1z; op[131] = w1w;

        float p = s0.x * w0x + s0.y * w0y + s0.z * w0z + s0.w * w0w
                + s1.x * w1x + s1.y * w1y + s1.z * w1z + s1.w * w1w;
        #pragma unroll
        for (int o = 16; o > 0; o >>= 1) p += __shfl_xor_sync(FULLM, p, o);
        warpDot += p;
    }

    if (lane == 0) wdots[wid] = warpDot;
    __syncthreads();
    if (tid == 0) {
        float t = 0.0f;
        #pragma unroll
        for (int i = 0; i < 32; i++) t += wdots[i];
        out[0] = 0.1f * (1.0f - t / Bf);
    }

    // Re-zero accumulators for the next (graph-replayed) invocation.
    __syncthreads();
    for (int i = tid; i < CC * DD; i += 1024) g_sums[i] = 0.0f;
    if (tid < CC) g_counts[tid] = 0.0f;
}

extern "C" void kernel_launch(void* const* d_in, const int* in_sizes, int n_in,
                              void* d_out, int out_size)
{
    const float* dirs    = (const float*)d_in[0];
    const float* v_class = (const float*)d_in[1];
    const int*   labels  = (const int*)d_in[2];
    const int*   step    = (const int*)d_in[3];
    int B = in_sizes[2];

    accum_kernel<<<GRID1, T1>>>(dirs, labels, B);
    finalize_kernel<<<1, 1024>>>(v_class, step, (float*)d_out, (float)B);
}

// round 5
// speedup vs baseline: 1.2923x; 1.2923x over previous
#include <cuda_runtime.h>

// PrototypeField: B=262144, D=256, C=128.
// out[0] = 0.1*(1 - mean cos_sim), out[1..32768] = new_v (C,D).
//
// Identity: sum_i <dirs_n_i, new_v[label_i]> = sum_c <sums_c, new_v_c>,
// so dirs is read exactly once (268 MB, HBM floor ~34us).
//
// accum_kernel (148x1024): phase A = ballot counting-sort of the CTA's label
// slice into per-class row lists (smem). Phase B = flat walk of the warp's
// sorted range with 1-row lookahead (8 live float4 -> no spills at 64-reg
// cap), flushing register accumulators to per-CTA partials with plain
// STG.128 at class boundaries. No atomics, no persistent state to zero.
// class_kernel (128x256): per class, reduce 148 partials + EMA + renorm +
// write new_v + dot.  loss_kernel: sum per-class dots -> out[0].

#define DD 256
#define CC 128
#define GRID1 148
#define T1 1024
#define FULLM 0xFFFFFFFFu
#define MAXROWS 1792

__device__ float g_part[GRID1 * CC * DD];   // fully overwritten each run
__device__ float g_pcnt[GRID1 * CC];        // fully overwritten each run
__device__ float g_dots[CC];                // fully overwritten each run

#define DOT8(p, q) ((p).x*(p).x + (p).y*(p).y + (p).z*(p).z + (p).w*(p).w \
                  + (q).x*(q).x + (q).y*(q).y + (q).z*(q).z + (q).w*(q).w)
#define AXPY4(acc, v, s) do { (acc).x += (v).x*(s); (acc).y += (v).y*(s); \
                              (acc).z += (v).z*(s); (acc).w += (v).w*(s); } while (0)

__global__ __launch_bounds__(T1, 1) void accum_kernel(
    const float* __restrict__ dirs,
    const int* __restrict__ labels,
    int B)
{
    __shared__ int labs[MAXROWS];
    __shared__ unsigned short list[MAXROWS];
    __shared__ int ccount[CC];
    __shared__ int cbase[CC + 1];

    const int tid  = threadIdx.x;
    const int wid  = tid >> 5;          // warp owns classes [4*wid, 4*wid+4)
    const int lane = tid & 31;
    const int base_c = wid << 2;

    const int rows_per = (B + GRID1 - 1) / GRID1;   // 1772
    const int row0  = blockIdx.x * rows_per;
    const int nrows = min(rows_per, B - row0);
    if (nrows <= 0) return;

    for (int i = tid; i < nrows; i += T1) labs[i] = labels[row0 + i];
    __syncthreads();

    // ---- Phase A1: per-class counts ----
    int c0 = 0, c1 = 0, c2 = 0, c3 = 0;
    for (int b = 0; b < nrows; b += 32) {
        int r = b + lane;
        int lab = (r < nrows) ? labs[r] : -1;
        c0 += __popc(__ballot_sync(FULLM, lab == base_c));
        c1 += __popc(__ballot_sync(FULLM, lab == base_c + 1));
        c2 += __popc(__ballot_sync(FULLM, lab == base_c + 2));
        c3 += __popc(__ballot_sync(FULLM, lab == base_c + 3));
    }
    if (lane == 0) {
        ccount[base_c]     = c0;
        ccount[base_c + 1] = c1;
        ccount[base_c + 2] = c2;
        ccount[base_c + 3] = c3;
    }
    __syncthreads();

    // ---- Phase A2: exclusive prefix over 128 class counts (warp 0) ----
    if (wid == 0) {
        int k0 = ccount[lane * 4], k1 = ccount[lane * 4 + 1];
        int k2 = ccount[lane * 4 + 2], k3 = ccount[lane * 4 + 3];
        int s = k0 + k1 + k2 + k3;
        int x = s;
        #pragma unroll
        for (int o = 1; o < 32; o <<= 1) {
            int y = __shfl_up_sync(FULLM, x, o);
            if (lane >= o) x += y;
        }
        int excl = x - s;
        cbase[lane * 4]     = excl;
        cbase[lane * 4 + 1] = excl + k0;
        cbase[lane * 4 + 2] = excl + k0 + k1;
        cbase[lane * 4 + 3] = excl + k0 + k1 + k2;
        if (lane == 31) cbase[CC] = excl + s;
    }
    __syncthreads();

    // ---- Phase A3: fill class-sorted row lists ----
    {
        int o0 = cbase[base_c],     o1 = cbase[base_c + 1];
        int o2 = cbase[base_c + 2], o3 = cbase[base_c + 3];
        unsigned below = (1u << lane) - 1u;
        for (int b = 0; b < nrows; b += 32) {
            int r = b + lane;
            int lab = (r < nrows) ? labs[r] : -1;
            unsigned m0 = __ballot_sync(FULLM, lab == base_c);
            unsigned m1 = __ballot_sync(FULLM, lab == base_c + 1);
            unsigned m2 = __ballot_sync(FULLM, lab == base_c + 2);
            unsigned m3 = __ballot_sync(FULLM, lab == base_c + 3);
            if (lab == base_c)          list[o0 + __popc(m0 & below)] = (unsigned short)r;
            else if (lab == base_c + 1) list[o1 + __popc(m1 & below)] = (unsigned short)r;
            else if (lab == base_c + 2) list[o2 + __popc(m2 & below)] = (unsigned short)r;
            else if (lab == base_c + 3) list[o3 + __popc(m3 & below)] = (unsigned short)r;
            o0 += __popc(m0); o1 += __popc(m1);
            o2 += __popc(m2); o3 += __popc(m3);
        }
    }
    __syncthreads();

    // ---- per-(cta,class) counts + zero partials of empty classes ----
    float* part_cta = g_part + blockIdx.x * (CC * DD);
    const float4 z = make_float4(0.f, 0.f, 0.f, 0.f);
    if (lane < 4) {
        int c = base_c + lane;
        g_pcnt[blockIdx.x * CC + c] = (float)(cbase[c + 1] - cbase[c]);
    }
    #pragma unroll
    for (int k = 0; k < 4; k++) {
        int c = base_c + k;
        if (cbase[c + 1] == cbase[c]) {
            float* pp = part_cta + c * DD + (lane << 2);
            *(float4*)pp = z;
            *(float4*)(pp + 128) = z;
        }
    }

    // ---- Phase B: flat walk with 1-row lookahead, flush at boundaries ----
    const int s0 = cbase[base_c], e0 = cbase[base_c + 4];
    if (s0 < e0) {
        const float4* dbase = (const float4*)dirs + (long long)row0 * (DD / 4);
        int cls = base_c;
        while (s0 >= cbase[cls + 1]) cls++;

        float4 AL = z, AH = z;
        const float4* p = dbase + (long long)list[s0] * 64;
        float4 a0 = __ldg(p + lane), a1 = __ldg(p + lane + 32);

        for (int i = s0; i < e0; i++) {
            float4 n0 = z, n1 = z;
            if (i + 1 < e0) {
                const float4* q = dbase + (long long)list[i + 1] * 64;
                n0 = __ldg(q + lane);
                n1 = __ldg(q + lane + 32);
            }

            float ss = DOT8(a0, a1);
            #pragma unroll
            for (int o = 16; o > 0; o >>= 1) ss += __shfl_xor_sync(FULLM, ss, o);
            float inv = 1.0f / fmaxf(sqrtf(ss), 1e-12f);
            AXPY4(AL, a0, inv);
            AXPY4(AH, a1, inv);

            if (i + 1 >= cbase[cls + 1]) {   // last row of class cls
                float* pp = part_cta + cls * DD + (lane << 2);
                *(float4*)pp = AL;
                *(float4*)(pp + 128) = AH;
                AL = z; AH = z;
                if (i + 1 < e0) {
                    cls++;
                    while (i + 1 >= cbase[cls + 1]) cls++;
                }
            }
            a0 = n0; a1 = n1;
        }
    }
}

__device__ __forceinline__ float block_sum256(float v, volatile float* red, int t)
{
    #pragma unroll
    for (int o = 16; o > 0; o >>= 1) v += __shfl_xor_sync(FULLM, v, o);
    __syncthreads();                 // protect red from previous use
    if ((t & 31) == 0) red[t >> 5] = v;
    __syncthreads();
    return red[0] + red[1] + red[2] + red[3] + red[4] + red[5] + red[6] + red[7];
}

__global__ __launch_bounds__(256, 4) void class_kernel(
    const float* __restrict__ v_class,
    const int* __restrict__ step_ptr,
    float* __restrict__ out,
    float Bf)
{
    __shared__ float red[8];
    const int c = blockIdx.x;
    const int t = threadIdx.x;       // dim index, 0..255

    // ---- reduce 148 partials (coalesced, unroll-4 for MLP) ----
    const float* pb = g_part + c * DD + t;
    float sA = 0.f, sB = 0.f, sC = 0.f, sD = 0.f;
    int j = 0;
    for (; j + 4 <= GRID1; j += 4) {
        sA += pb[(j + 0) * (CC * DD)];
        sB += pb[(j + 1) * (CC * DD)];
        sC += pb[(j + 2) * (CC * DD)];
        sD += pb[(j + 3) * (CC * DD)];
    }
    for (; j < GRID1; j++) sA += pb[j * (CC * DD)];
    float s = (sA + sB) + (sC + sD);          // sums_c[t]

    float cv = (t < GRID1) ? g_pcnt[t * CC + c] : 0.f;
    float cnt = block_sum256(cv, red, t);

    float stepf = (float)(*step_ptr);
    float alpha = fminf(0.02f, stepf / (stepf + 50.0f));
    float oma = 1.0f - alpha;

    float invc = 1.0f / fmaxf(cnt, 1.0f);
    float bm = s * invc;

    float nb = block_sum256(bm * bm, red, t);
    float invb = 1.0f / fmaxf(sqrtf(nb), 1e-12f);

    float vc = v_class[c * DD + t];
    float u = oma * vc + alpha * bm * invb;

    float nu = block_sum256(u * u, red, t);
    float invu = 1.0f / fmaxf(sqrtf(nu), 1e-12f);

    float w = (cnt > 0.0f) ? u * invu : vc;
    out[1 + c * DD + t] = w;

    float dot = block_sum256(s * w, red, t);
    if (t == 0) g_dots[c] = dot;
}

__global__ void loss_kernel(float* __restrict__ out, float Bf)
{
    __shared__ float red[4];
    const int t = threadIdx.x;       // 0..127
    float v = g_dots[t];
    #pragma unroll
    for (int o = 16; o > 0; o >>= 1) v += __shfl_xor_sync(FULLM, v, o);
    if ((t & 31) == 0) red[t >> 5] = v;
    __syncthreads();
    if (t == 0)
        out[0] = 0.1f * (1.0f - (red[0] + red[1] + red[2] + red[3]) / Bf);
}

extern "C" void kernel_launch(void* const* d_in, const int* in_sizes, int n_in,
                              void* d_out, int out_size)
{
    const float* dirs    = (const float*)d_in[0];
    const float* v_class = (const float*)d_in[1];
    const int*   labels  = (const int*)d_in[2];
    const int*   step    = (const int*)d_in[3];
    int B = in_sizes[2];

    accum_kernel<<<GRID1, T1>>>(dirs, labels, B);
    class_kernel<<<CC, 256>>>(v_class, step, (float*)d_out, (float)B);
    loss_kernel<<<1, 128>>>((float*)d_out, (float)B);
}